// round 2
// baseline (speedup 1.0000x reference)
#include <cuda_runtime.h>

#define DIM 256
#define MAXM 16384
#define MAXN 4096
#define BM 64
#define BN 128
#define BK 32
#define SMEM_BYTES ((DIM*BM + 2*BK*BN) * (int)sizeof(float))   // 64KB A + 2x16KB B = 96KB

// __device__ scratch (allocation-free rule)
__device__ float  g_VT[(size_t)DIM * MAXM];   // v transposed  [k][m]
__device__ float  g_WT[(size_t)DIM * MAXN];   // codebook transposed [k][n]
__device__ float  g_c2[MAXN];
__device__ float  g_v2[MAXM];
__device__ double g_loss;

__global__ void k_zero(double* p) { if (threadIdx.x == 0) *p = 0.0; }

// 32x32 smem tile transpose: src [R][DIM] row-major -> dst [DIM][R]
__global__ void k_transpose(const float* __restrict__ src, float* __restrict__ dst, int R) {
    __shared__ float tile[32][33];
    int kb = blockIdx.x * 32;
    int rb = blockIdx.y * 32;
    int tx = threadIdx.x, ty = threadIdx.y;
    #pragma unroll
    for (int j = 0; j < 32; j += 8)
        tile[ty + j][tx] = src[(size_t)(rb + ty + j) * DIM + kb + tx];
    __syncthreads();
    #pragma unroll
    for (int j = 0; j < 32; j += 8)
        dst[(size_t)(kb + ty + j) * R + rb + tx] = tile[tx][ty + j];
}

// per-row sum of squares (fp32, like reference) ; block (32,8)
__global__ void k_sumsq(const float* __restrict__ src, float* __restrict__ out, int R) {
    int row = blockIdx.x * 8 + threadIdx.y;
    if (row >= R) return;
    int lane = threadIdx.x;
    const float* p = src + (size_t)row * DIM;
    float s = 0.f;
    #pragma unroll
    for (int i = 0; i < DIM; i += 32) { float x = p[i + lane]; s = fmaf(x, x, s); }
    #pragma unroll
    for (int o = 16; o; o >>= 1) s += __shfl_xor_sync(0xffffffffu, s, o);
    if (lane == 0) out[row] = s;
}

__global__ void __launch_bounds__(256, 2)
k_vq_main(const float* __restrict__ v, const float* __restrict__ w,
          const float* __restrict__ VT, const float* __restrict__ WT,
          const float* __restrict__ c2, const float* __restrict__ v2,
          float* __restrict__ dout, double* __restrict__ lossAcc,
          int M, int N, long long idxBase)
{
    extern __shared__ float smem[];
    float* As = smem;                 // [256][64]
    float* Bs = smem + DIM * BM;      // 2 x [32][128]

    const int tid  = threadIdx.x;
    const int lane = tid & 31;
    const int rg   = tid >> 5;        // warp id = row group (8 rows each)
    const int cg   = lane;            // code group (4 codes each)
    const int row0 = blockIdx.x * BM;

    // Load A panel (64 rows x 256 k) from transposed V: coalesced, conflict-free
    #pragma unroll
    for (int j = 0; j < 16; j++) {
        int i  = tid + j * 256;
        int k  = i >> 4;
        int r4 = (i & 15) << 2;
        *(float4*)(As + k * BM + r4) =
            *(const float4*)(VT + (size_t)k * M + row0 + r4);
    }

    float v2r[8];
    #pragma unroll
    for (int r = 0; r < 8; r++) v2r[r] = __ldg(&v2[row0 + rg * 8 + r]);

    unsigned long long best[8];
    #pragma unroll
    for (int r = 0; r < 8; r++) best[r] = 0xFFFFFFFFFFFFFFFFULL;

    const int NT = N / BN;
    for (int nt = 0; nt < NT; nt++) {
        const int code0 = nt * BN;
        float acc[8][4];
        #pragma unroll
        for (int r = 0; r < 8; r++)
            #pragma unroll
            for (int c = 0; c < 4; c++) acc[r][c] = 0.f;

        // preload kt = 0
        #pragma unroll
        for (int j = 0; j < 4; j++) {
            int i  = tid + j * 256;
            int k  = i >> 5;
            int c4 = (i & 31) << 2;
            *(float4*)(Bs + k * BN + c4) =
                *(const float4*)(WT + (size_t)k * N + code0 + c4);
        }
        __syncthreads();

        #pragma unroll 1
        for (int kt = 0; kt < DIM / BK; kt++) {
            float4 pre[4];
            if (kt < DIM / BK - 1) {
                #pragma unroll
                for (int j = 0; j < 4; j++) {
                    int i  = tid + j * 256;
                    int k  = i >> 5;
                    int c4 = (i & 31) << 2;
                    pre[j] = *(const float4*)(WT + (size_t)((kt + 1) * BK + k) * N + code0 + c4);
                }
            }
            const float* Bcur = Bs + (kt & 1) * BK * BN;
            const int kb = kt * BK;
            #pragma unroll 8
            for (int kk = 0; kk < BK; kk++) {
                float4 a0 = *(const float4*)(As + (kb + kk) * BM + rg * 8);
                float4 a1 = *(const float4*)(As + (kb + kk) * BM + rg * 8 + 4);
                float4 b  = *(const float4*)(Bcur + kk * BN + cg * 4);
                float av[8] = {a0.x, a0.y, a0.z, a0.w, a1.x, a1.y, a1.z, a1.w};
                float bv[4] = {b.x, b.y, b.z, b.w};
                #pragma unroll
                for (int r = 0; r < 8; r++)
                    #pragma unroll
                    for (int c = 0; c < 4; c++)
                        acc[r][c] = fmaf(av[r], bv[c], acc[r][c]);
            }
            if (kt < DIM / BK - 1) {
                float* Bnxt = Bs + ((kt + 1) & 1) * BK * BN;
                #pragma unroll
                for (int j = 0; j < 4; j++) {
                    int i  = tid + j * 256;
                    int k  = i >> 5;
                    int c4 = (i & 31) << 2;
                    *(float4*)(Bnxt + k * BN + c4) = pre[j];
                }
            }
            __syncthreads();
        }

        // argmin epilogue for this N-tile: score = fp32((v2 - 2*dot) + c2), mimic ref op order
        #pragma unroll
        for (int c = 0; c < 4; c++) {
            int code = code0 + cg * 4 + c;
            float c2c = __ldg(&c2[code]);
            #pragma unroll
            for (int r = 0; r < 8; r++) {
                float score = __fadd_rn(__fsub_rn(v2r[r], __fmul_rn(2.0f, acc[r][c])), c2c);
                unsigned u = __float_as_uint(score);
                u = (u & 0x80000000u) ? ~u : (u | 0x80000000u);
                unsigned long long key = ((unsigned long long)u << 32) | (unsigned)code;
                if (code != 0 && key < best[r]) best[r] = key;   // code 0 excluded like ref
            }
        }
    }

    // warp-wide min (each warp owns rows rg*8 .. rg*8+7 fully)
    #pragma unroll
    for (int r = 0; r < 8; r++) {
        unsigned long long k = best[r];
        #pragma unroll
        for (int o = 16; o; o >>= 1) {
            unsigned long long other = __shfl_xor_sync(0xffffffffu, k, o);
            if (other < k) k = other;
        }
        best[r] = k;
    }

    // final epilogue: mask check, gather, write out/idx, loss accumulation
    double ls = 0.0;
    const float CEQ = 0.00390625f;  // 1/256, exactly representable
    #pragma unroll 1
    for (int r = 0; r < 8; r++) {
        int row  = row0 + rg * 8 + r;
        int code = (int)(best[r] & 0xFFFFFFFFULL);
        const float4* vr = (const float4*)(v + (size_t)row * DIM);
        float4 x0 = vr[lane * 2], x1 = vr[lane * 2 + 1];
        bool alleq = (x0.x == CEQ) && (x0.y == CEQ) && (x0.z == CEQ) && (x0.w == CEQ) &&
                     (x1.x == CEQ) && (x1.y == CEQ) && (x1.z == CEQ) && (x1.w == CEQ);
        if (__all_sync(0xffffffffu, alleq)) code = 0;

        const float4* cr = (const float4*)(w + (size_t)code * DIM);
        float4 o0 = cr[lane * 2], o1 = cr[lane * 2 + 1];
        float4* orow = (float4*)(dout + (size_t)row * DIM);
        orow[lane * 2]     = o0;
        orow[lane * 2 + 1] = o1;
        if (idxBase >= 0 && lane == 0) dout[idxBase + row] = (float)code;

        float d;
        d = o0.x - x0.x; ls += (double)d * d;
        d = o0.y - x0.y; ls += (double)d * d;
        d = o0.z - x0.z; ls += (double)d * d;
        d = o0.w - x0.w; ls += (double)d * d;
        d = o1.x - x1.x; ls += (double)d * d;
        d = o1.y - x1.y; ls += (double)d * d;
        d = o1.z - x1.z; ls += (double)d * d;
        d = o1.w - x1.w; ls += (double)d * d;
    }
    #pragma unroll
    for (int o = 16; o; o >>= 1) ls += __shfl_xor_sync(0xffffffffu, ls, o);
    if (lane == 0) atomicAdd(lossAcc, ls);
}

__global__ void k_fin(float* dout, const double* lossAcc,
                      long long lossPos, long long usedPos, double invCnt) {
    if (threadIdx.x == 0) {
        if (lossPos >= 0) dout[lossPos] = (float)(*lossAcc * invCnt);
        if (usedPos >= 0) dout[usedPos] = 0.0f;
    }
}

extern "C" void kernel_launch(void* const* d_in, const int* in_sizes, int n_in,
                              void* d_out, int out_size)
{
    const float* v = (const float*)d_in[0];
    const float* w = (const float*)d_in[1];
    const int M = in_sizes[0] / DIM;   // 16384
    const int N = in_sizes[1] / DIM;   // 4096
    float* out = (float*)d_out;

    float *pVT, *pWT, *pC2, *pV2; double* pLoss;
    cudaGetSymbolAddress((void**)&pVT, g_VT);
    cudaGetSymbolAddress((void**)&pWT, g_WT);
    cudaGetSymbolAddress((void**)&pC2, g_c2);
    cudaGetSymbolAddress((void**)&pV2, g_v2);
    cudaGetSymbolAddress((void**)&pLoss, g_loss);

    long long base = (long long)M * DIM;
    long long idxBase = -1, lossPos = -1, usedPos = -1;
    if ((long long)out_size >= base + M)     idxBase = base;
    if ((long long)out_size >= base + M + 1) lossPos = base + M;
    if ((long long)out_size >= base + M + 2) usedPos = base + M + 1;

    k_zero<<<1, 32>>>(pLoss);

    dim3 tb(32, 8);
    k_transpose<<<dim3(DIM / 32, M / 32), tb>>>(v, pVT, M);
    k_transpose<<<dim3(DIM / 32, N / 32), tb>>>(w, pWT, N);
    k_sumsq<<<(M + 7) / 8, tb>>>(v, pV2, M);
    k_sumsq<<<(N + 7) / 8, tb>>>(w, pC2, N);

    cudaFuncSetAttribute(k_vq_main, cudaFuncAttributeMaxDynamicSharedMemorySize, SMEM_BYTES);
    k_vq_main<<<M / BM, 256, SMEM_BYTES>>>(v, w, pVT, pWT, pC2, pV2,
                                           out, pLoss, M, N, idxBase);

    k_fin<<<1, 32>>>(out, pLoss, lossPos, usedPos, 1.0 / ((double)M * DIM));
}

// round 4
// speedup vs baseline: 1.0804x; 1.0804x over previous
#include <cuda_runtime.h>
#include <cuda_bf16.h>
#include <cstdint>

#define DIM 256
#define MT 16384
#define NTOT 4096
#define TH_GAP 2e-3f
#define NSTAGES 128            // 32 n-tiles * 4 k-chunks
#define SM_A_HI 0
#define SM_A_LO 65536
#define SM_B 131072
#define STAGE_BYTES 32768      // (128n x 64k) bf16, hi(16KB)+lo(16KB)
#define SMEM_TOTAL 196608

__device__ __nv_bfloat16 g_Whi[(size_t)NTOT*DIM];
__device__ __nv_bfloat16 g_Wlo[(size_t)NTOT*DIM];
__device__ float  g_WT[(size_t)DIM*NTOT];
__device__ float  g_c2[NTOT];
__device__ float  g_v2[MT];
__device__ int    g_code[MT];
__device__ int    g_fb[MT];
__device__ int    g_fbn;
__device__ double g_loss;

__device__ __forceinline__ uint32_t smem_u32(const void* p){
    uint32_t a; asm("{ .reg .u64 t; cvta.to.shared.u64 t,%1; cvt.u32.u64 %0,t; }":"=r"(a):"l"(p)); return a;
}
__device__ __forceinline__ uint32_t lds32(uint32_t a){
    uint32_t v; asm volatile("ld.shared.b32 %0,[%1];":"=r"(v):"r"(a)); return v;
}
__device__ __forceinline__ void mma16816(float* c, uint32_t a0,uint32_t a1,uint32_t a2,uint32_t a3,
                                         uint32_t b0,uint32_t b1){
    asm volatile("mma.sync.aligned.m16n8k16.row.col.f32.bf16.bf16.f32 "
        "{%0,%1,%2,%3},{%4,%5,%6,%7},{%8,%9},{%0,%1,%2,%3};"
        :"+f"(c[0]),"+f"(c[1]),"+f"(c[2]),"+f"(c[3])
        :"r"(a0),"r"(a1),"r"(a2),"r"(a3),"r"(b0),"r"(b1));
}
__device__ __forceinline__ uint32_t packbf(__nv_bfloat16 a, __nv_bfloat16 b){
    return (uint32_t)__bfloat16_as_ushort(a) | ((uint32_t)__bfloat16_as_ushort(b)<<16);
}
__device__ __forceinline__ unsigned long long mkkey(float s, int code){
    if(code==0) return ~0ULL;
    unsigned u=__float_as_uint(s);
    u=(u&0x80000000u)?~u:(u|0x80000000u);
    return ((unsigned long long)u<<32)|(unsigned)code;
}
__device__ __forceinline__ float keyf(unsigned long long k){
    unsigned u=(unsigned)(k>>32);
    return (u&0x80000000u)?__uint_as_float(u&0x7FFFFFFFu):__uint_as_float(~u);
}
__device__ __forceinline__ void upd(unsigned long long&b1,unsigned long long&b2,unsigned long long k){
    if(k<b1){b2=b1;b1=k;} else if(k<b2){b2=k;}
}

// ---------- prep ----------
__global__ void k_zero(double* pl, int* pc){ if(threadIdx.x==0){ *pl=0.0; *pc=0; } }

__global__ void k_transpose(const float* __restrict__ src, float* __restrict__ dst, int R){
    __shared__ float tile[32][33];
    int kb=blockIdx.x*32, rb=blockIdx.y*32, tx=threadIdx.x, ty=threadIdx.y;
    #pragma unroll
    for(int j=0;j<32;j+=8) tile[ty+j][tx]=src[(size_t)(rb+ty+j)*DIM+kb+tx];
    __syncthreads();
    #pragma unroll
    for(int j=0;j<32;j+=8) dst[(size_t)(kb+ty+j)*R+rb+tx]=tile[tx][ty+j];
}

__global__ void k_sumsq(const float* __restrict__ src, float* __restrict__ out, int R){
    int row=blockIdx.x*8+threadIdx.y; if(row>=R)return;
    int lane=threadIdx.x; const float* p=src+(size_t)row*DIM; float s=0.f;
    #pragma unroll
    for(int i=0;i<DIM;i+=32){ float x=p[i+lane]; s=fmaf(x,x,s); }
    #pragma unroll
    for(int o=16;o;o>>=1) s+=__shfl_xor_sync(0xffffffffu,s,o);
    if(lane==0) out[row]=s;
}

__global__ void k_wsplit(const float* __restrict__ w, __nv_bfloat16* __restrict__ hi,
                         __nv_bfloat16* __restrict__ lo){
    int i=blockIdx.x*256+threadIdx.x;
    float f=w[i];
    __nv_bfloat16 h=__float2bfloat16(f);
    hi[i]=h; lo[i]=__float2bfloat16(f-__bfloat162float(h));
}

// ---------- main GEMM + argmin ----------
__global__ void __launch_bounds__(256,1)
k_main(const float* __restrict__ v, const __nv_bfloat16* __restrict__ Whi,
       const __nv_bfloat16* __restrict__ Wlo, const float* __restrict__ c2)
{
    extern __shared__ char smem[];
    uint32_t sb=smem_u32(smem);
    int tid=threadIdx.x, lane=tid&31, wid=tid>>5;
    int g=lane>>2, q=lane&3;
    int row0=blockIdx.x*128;

    // fill A panel (hi/lo bf16, swizzled)
    for(int i=tid;i<8192;i+=256){
        int e=i*4, r=e>>8, k=e&255;
        float4 f=*(const float4*)(v+(size_t)(row0+r)*DIM+k);
        __nv_bfloat16 h0=__float2bfloat16(f.x),h1=__float2bfloat16(f.y),
                      h2=__float2bfloat16(f.z),h3=__float2bfloat16(f.w);
        __nv_bfloat16 l0=__float2bfloat16(f.x-__bfloat162float(h0)),
                      l1=__float2bfloat16(f.y-__bfloat162float(h1)),
                      l2=__float2bfloat16(f.z-__bfloat162float(h2)),
                      l3=__float2bfloat16(f.w-__bfloat162float(h3));
        uint2 hp=make_uint2(packbf(h0,h1),packbf(h2,h3));
        uint2 lp=make_uint2(packbf(l0,l1),packbf(l2,l3));
        uint32_t byte=(uint32_t)r*512u + (uint32_t)((((k>>1)^((r&7)<<2)))<<2);
        *(uint2*)(smem+SM_A_HI+byte)=hp;
        *(uint2*)(smem+SM_A_LO+byte)=lp;
    }

    auto ld_stage=[&](int s){
        int nt=s>>2, kc=(s&3)*64, n0=nt*128;
        uint32_t base=sb+SM_B+(uint32_t)(s&1)*STAGE_BYTES;
        #pragma unroll
        for(int j=0;j<8;j++){
            int idx=j*256+tid, mat=idx>>10, rem=idx&1023, n=rem>>3, m=rem&7;
            const __nv_bfloat16* src=(mat?Wlo:Whi)+(size_t)(n0+n)*DIM+kc+m*8;
            uint32_t dst=base+(uint32_t)mat*16384u+(uint32_t)n*128u
                         +(uint32_t)((((m*4)^((n&7)<<2)))<<2);
            asm volatile("cp.async.cg.shared.global [%0],[%1],16;"::"r"(dst),"l"(src):"memory");
        }
        asm volatile("cp.async.commit_group;":::"memory");
    };

    ld_stage(0);

    float acc[16][4];
    unsigned long long bA1=~0ULL,bA2=~0ULL,bB1=~0ULL,bB2=~0ULL;
    const int r0=wid*16+g;
    const uint32_t sw=(uint32_t)((r0&7)<<2);        // (r0+8)&7 == r0&7
    const uint32_t aH=sb+SM_A_HI+(uint32_t)r0*512u;
    const uint32_t aL=sb+SM_A_LO+(uint32_t)r0*512u;
    const uint32_t gsw=(uint32_t)(g<<2);

    #pragma unroll 1
    for(int s=0;s<NSTAGES;s++){
        if(s+1<NSTAGES){
            ld_stage(s+1);
            asm volatile("cp.async.wait_group 1;":::"memory");
        } else {
            asm volatile("cp.async.wait_group 0;":::"memory");
        }
        __syncthreads();

        if((s&3)==0){
            #pragma unroll
            for(int nt=0;nt<16;nt++){acc[nt][0]=0.f;acc[nt][1]=0.f;acc[nt][2]=0.f;acc[nt][3]=0.f;}
        }
        const uint32_t bbase=sb+SM_B+(uint32_t)(s&1)*STAGE_BYTES;
        const int kc=(s&3)*64;

        #pragma unroll
        for(int st=0;st<4;st++){
            int w0=(kc>>1)+st*8;
            uint32_t oa=(uint32_t)(((w0+q)^sw)<<2);
            uint32_t ob=(uint32_t)(((w0+q+4)^sw)<<2);
            uint32_t ah0=lds32(aH+oa),      ah1=lds32(aH+4096u+oa);
            uint32_t ah2=lds32(aH+ob),      ah3=lds32(aH+4096u+ob);
            uint32_t al0=lds32(aL+oa),      al1=lds32(aL+4096u+oa);
            uint32_t al2=lds32(aL+ob),      al3=lds32(aL+4096u+ob);
            uint32_t wb0=(uint32_t)(((st*8+q)^gsw)<<2);
            uint32_t wb1=(uint32_t)(((st*8+q+4)^gsw)<<2);
            #pragma unroll
            for(int nt=0;nt<16;nt++){
                uint32_t brow=bbase+(uint32_t)(nt*8+g)*128u;
                uint32_t bh0=lds32(brow+wb0), bh1=lds32(brow+wb1);
                uint32_t bl0=lds32(brow+16384u+wb0), bl1=lds32(brow+16384u+wb1);
                mma16816(acc[nt],ah0,ah1,ah2,ah3,bh0,bh1);
                mma16816(acc[nt],al0,al1,al2,al3,bh0,bh1);
                mma16816(acc[nt],ah0,ah1,ah2,ah3,bl0,bl1);
            }
        }

        if((s&3)==3){
            int cb=(s>>2)*128;
            #pragma unroll
            for(int nt=0;nt<16;nt++){
                int c=cb+nt*8+q*2;
                float c20=__ldg(c2+c), c21=__ldg(c2+c+1);
                upd(bA1,bA2,mkkey(fmaf(-2.f,acc[nt][0],c20),c));
                upd(bA1,bA2,mkkey(fmaf(-2.f,acc[nt][1],c21),c+1));
                upd(bB1,bB2,mkkey(fmaf(-2.f,acc[nt][2],c20),c));
                upd(bB1,bB2,mkkey(fmaf(-2.f,acc[nt][3],c21),c+1));
            }
        }
        __syncthreads();
    }

    // quad reduction (lanes q=0..3 hold same rows)
    #pragma unroll
    for(int o=1;o<=2;o<<=1){
        unsigned long long o1,o2;
        o1=__shfl_xor_sync(0xffffffffu,bA1,o); o2=__shfl_xor_sync(0xffffffffu,bA2,o);
        { unsigned long long n1=min(bA1,o1), n2=min(max(bA1,o1),min(bA2,o2)); bA1=n1; bA2=n2; }
        o1=__shfl_xor_sync(0xffffffffu,bB1,o); o2=__shfl_xor_sync(0xffffffffu,bB2,o);
        { unsigned long long n1=min(bB1,o1), n2=min(max(bB1,o1),min(bB2,o2)); bB1=n1; bB2=n2; }
    }
    if(q==0){
        int rA=row0+r0, rB=rA+8;
        g_code[rA]=(int)(bA1&0xFFFFFFFFu);
        if(keyf(bA2)-keyf(bA1)<TH_GAP){ int p=atomicAdd(&g_fbn,1); g_fb[p]=rA; }
        g_code[rB]=(int)(bB1&0xFFFFFFFFu);
        if(keyf(bB2)-keyf(bB1)<TH_GAP){ int p=atomicAdd(&g_fbn,1); g_fb[p]=rB; }
    }
}

// ---------- exact fp32 fallback ----------
__global__ void k_fb(const float* __restrict__ v, const float* __restrict__ WT,
                     const float* __restrict__ c2, const float* __restrict__ v2){
    __shared__ float vs[DIM];
    __shared__ unsigned long long red[256];
    int nfb=g_fbn;
    for(int it=blockIdx.x; it<nfb; it+=gridDim.x){
        int row=g_fb[it];
        for(int i=threadIdx.x;i<DIM;i+=256) vs[i]=v[(size_t)row*DIM+i];
        __syncthreads();
        float v2r=v2[row];
        unsigned long long best=~0ULL;
        for(int n=threadIdx.x;n<NTOT;n+=256){
            if(n==0) continue;
            float dot=0.f;
            #pragma unroll 8
            for(int k=0;k<DIM;k++) dot=fmaf(vs[k],WT[(size_t)k*NTOT+n],dot);
            float s=__fadd_rn(__fsub_rn(v2r,__fmul_rn(2.0f,dot)),c2[n]);
            unsigned u=__float_as_uint(s); u=(u&0x80000000u)?~u:(u|0x80000000u);
            unsigned long long key=((unsigned long long)u<<32)|(unsigned)n;
            if(key<best)best=key;
        }
        red[threadIdx.x]=best; __syncthreads();
        #pragma unroll
        for(int o=128;o;o>>=1){
            if(threadIdx.x<o && red[threadIdx.x+o]<red[threadIdx.x]) red[threadIdx.x]=red[threadIdx.x+o];
            __syncthreads();
        }
        if(threadIdx.x==0) g_code[row]=(int)(red[0]&0xFFFFFFFFu);
        __syncthreads();
    }
}

// ---------- gather + loss ----------
__global__ void k_gather(const float* __restrict__ v, const float* __restrict__ w,
                         float* __restrict__ dout, double* __restrict__ lossAcc,
                         long long idxBase){
    int wy=threadIdx.y, lane=threadIdx.x;
    int row=blockIdx.x*8+wy;
    const float4* vr=(const float4*)(v+(size_t)row*DIM);
    float4 x0=vr[lane*2], x1=vr[lane*2+1];
    const float CEQ=0.00390625f;
    bool alleq=(x0.x==CEQ)&&(x0.y==CEQ)&&(x0.z==CEQ)&&(x0.w==CEQ)&&
               (x1.x==CEQ)&&(x1.y==CEQ)&&(x1.z==CEQ)&&(x1.w==CEQ);
    int code=g_code[row];
    if(__all_sync(0xffffffffu,alleq)) code=0;
    const float4* cr=(const float4*)(w+(size_t)code*DIM);
    float4 o0=cr[lane*2], o1=cr[lane*2+1];
    float4* orow=(float4*)(dout+(size_t)row*DIM);
    orow[lane*2]=o0; orow[lane*2+1]=o1;
    if(idxBase>=0&&lane==0) dout[idxBase+row]=(float)code;
    double ls=0.0; float d;
    d=o0.x-x0.x; ls+=(double)d*d; d=o0.y-x0.y; ls+=(double)d*d;
    d=o0.z-x0.z; ls+=(double)d*d; d=o0.w-x0.w; ls+=(double)d*d;
    d=o1.x-x1.x; ls+=(double)d*d; d=o1.y-x1.y; ls+=(double)d*d;
    d=o1.z-x1.z; ls+=(double)d*d; d=o1.w-x1.w; ls+=(double)d*d;
    #pragma unroll
    for(int o=16;o;o>>=1) ls+=__shfl_xor_sync(0xffffffffu,ls,o);
    if(lane==0) atomicAdd(lossAcc,ls);
}

__global__ void k_fin(float* dout, const double* lossAcc,
                      long long lossPos, long long usedPos, double invCnt){
    if(threadIdx.x==0){
        if(lossPos>=0) dout[lossPos]=(float)(*lossAcc*invCnt);
        if(usedPos>=0) dout[usedPos]=0.0f;
    }
}

extern "C" void kernel_launch(void* const* d_in, const int* in_sizes, int n_in,
                              void* d_out, int out_size)
{
    const float* v=(const float*)d_in[0];
    const float* w=(const float*)d_in[1];
    const int M=in_sizes[0]/DIM, N=in_sizes[1]/DIM;
    float* out=(float*)d_out;

    __nv_bfloat16 *pWhi,*pWlo; float *pWT,*pC2,*pV2; int* pFbn; double* pLoss;
    cudaGetSymbolAddress((void**)&pWhi,g_Whi);
    cudaGetSymbolAddress((void**)&pWlo,g_Wlo);
    cudaGetSymbolAddress((void**)&pWT,g_WT);
    cudaGetSymbolAddress((void**)&pC2,g_c2);
    cudaGetSymbolAddress((void**)&pV2,g_v2);
    cudaGetSymbolAddress((void**)&pFbn,g_fbn);
    cudaGetSymbolAddress((void**)&pLoss,g_loss);

    long long base=(long long)M*DIM;
    long long idxBase=-1,lossPos=-1,usedPos=-1;
    if((long long)out_size>=base+M)   idxBase=base;
    if((long long)out_size>=base+M+1) lossPos=base+M;
    if((long long)out_size>=base+M+2) usedPos=base+M+1;

    dim3 tb(32,8);
    k_zero<<<1,32>>>(pLoss,pFbn);
    k_sumsq<<<M/8,tb>>>(v,pV2,M);
    k_sumsq<<<N/8,tb>>>(w,pC2,N);
    k_transpose<<<dim3(DIM/32,N/32),tb>>>(w,pWT,N);
    k_wsplit<<<(N*DIM)/256,256>>>(w,pWhi,pWlo);

    cudaFuncSetAttribute(k_main,cudaFuncAttributeMaxDynamicSharedMemorySize,SMEM_TOTAL);
    k_main<<<M/128,256,SMEM_TOTAL>>>(v,pWhi,pWlo,pC2);

    k_fb<<<256,256>>>(v,pWT,pC2,pV2);
    k_gather<<<M/8,tb>>>(v,w,out,pLoss,idxBase);
    k_fin<<<1,32>>>(out,pLoss,lossPos,usedPos,1.0/((double)M*DIM));
}